// round 2
// baseline (speedup 1.0000x reference)
#include <cuda_runtime.h>

// Locally-connected conv: out[b,o,h,w] = sum_{c,i,j} W[h,w,o,c,i,j]*xpad[b,c,h+i,w+j] + bias[o,h,w]
// Per (h,w): GEMM  M=B=32, N=COUT=64, K=288.

#define B_     32
#define CIN_   32
#define IH_    64
#define IW_    64
#define COUT_  64
#define OH_    64
#define OW_    64
#define KTOT   288   // CIN_*3*3
#define KC     32    // K-chunk
#define NCHUNK 9     // KTOT/KC

__global__ __launch_bounds__(128, 1)
void lc_conv_kernel(const float* __restrict__ x,
                    const float* __restrict__ wgt,
                    const float* __restrict__ bias,
                    float* __restrict__ out)
{
    __shared__ float patch_s[KTOT][B_];   // 288*32*4 = 36864 B, [k][b]
    __shared__ float ws[KC][COUT_];       // 32*64*4  =  8192 B, [k][o] (transposed chunk)

    const int w = blockIdx.x;
    const int h = blockIdx.y;
    const int t = threadIdx.x;

    // ---------------- load patches into smem (transposed [k][b]) ----------------
    // idx runs over (c,i,b): 32*3*32 = 3072 units, 24 per thread.
    for (int idx = t; idx < CIN_ * 3 * B_; idx += 128) {
        int b  = idx & 31;
        int ci = idx >> 5;          // c*3 + i
        int c  = ci / 3;
        int i  = ci - c * 3;
        int row = h + i - 1;
        int kbase = c * 9 + i * 3;
        if ((unsigned)row < IH_) {
            const float* xp = x + ((b * CIN_ + c) * IH_ + row) * IW_;
#pragma unroll
            for (int j = 0; j < 3; j++) {
                int col = w + j - 1;
                patch_s[kbase + j][b] = ((unsigned)col < IW_) ? xp[col] : 0.0f;
            }
        } else {
#pragma unroll
            for (int j = 0; j < 3; j++) patch_s[kbase + j][b] = 0.0f;
        }
    }

    // ---------------- weight streaming setup ----------------
    // This position's weight block: COUT_ rows of KTOT floats, contiguous.
    const float4* wbase = (const float4*)(wgt + (size_t)(h * OW_ + w) * COUT_ * KTOT);
    const int lo    = t & 63;   // row (o) this thread loads
    const int lhalf = t >> 6;   // which half of the 32-float chunk (16 floats)
    // per chunk kc: thread loads row lo, float4s [kc*8 + lhalf*4 .. +3]

    float4 r0, r1, r2, r3;
    {   // prefetch chunk 0 (overlaps the patch-load loop above)
        const float4* p = wbase + lo * (KTOT / 4) + lhalf * 4;
        r0 = p[0]; r1 = p[1]; r2 = p[2]; r3 = p[3];
    }

    const int bg = t & 7;       // b0 = bg*4
    const int og = t >> 3;      // o0 = og*4
    const int b0 = bg * 4;
    const int o0 = og * 4;

    float acc[4][4];
#pragma unroll
    for (int i = 0; i < 4; i++)
#pragma unroll
        for (int j = 0; j < 4; j++) acc[i][j] = 0.0f;

    // ---------------- main loop over K chunks ----------------
    for (int kc = 0; kc < NCHUNK; kc++) {
        __syncthreads();   // prev compute done (kc==0: also fences patch stores)

        // store prefetched chunk, transposed to ws[k][o] (conflict-free: lanes have
        // consecutive `lo` for fixed k-row)
        {
            int kb = lhalf * 16;
            ws[kb +  0][lo] = r0.x; ws[kb +  1][lo] = r0.y;
            ws[kb +  2][lo] = r0.z; ws[kb +  3][lo] = r0.w;
            ws[kb +  4][lo] = r1.x; ws[kb +  5][lo] = r1.y;
            ws[kb +  6][lo] = r1.z; ws[kb +  7][lo] = r1.w;
            ws[kb +  8][lo] = r2.x; ws[kb +  9][lo] = r2.y;
            ws[kb + 10][lo] = r2.z; ws[kb + 11][lo] = r2.w;
            ws[kb + 12][lo] = r3.x; ws[kb + 13][lo] = r3.y;
            ws[kb + 14][lo] = r3.z; ws[kb + 15][lo] = r3.w;
        }
        __syncthreads();

        // issue next chunk's global loads early (latency hidden under compute)
        if (kc + 1 < NCHUNK) {
            const float4* p = wbase + lo * (KTOT / 4) + (kc + 1) * 8 + lhalf * 4;
            r0 = p[0]; r1 = p[1]; r2 = p[2]; r3 = p[3];
        }

        // compute: 32 k-steps, each 2x LDS.128 + 16 FFMA
#pragma unroll
        for (int k = 0; k < KC; k++) {
            float4 av = *(const float4*)&patch_s[kc * KC + k][b0];
            float4 wv = *(const float4*)&ws[k][o0];
            float a[4] = {av.x, av.y, av.z, av.w};
            float wr[4] = {wv.x, wv.y, wv.z, wv.w};
#pragma unroll
            for (int bb = 0; bb < 4; bb++)
#pragma unroll
                for (int oo = 0; oo < 4; oo++)
                    acc[bb][oo] = fmaf(a[bb], wr[oo], acc[bb][oo]);
        }
    }

    // ---------------- epilogue: bias + store ----------------
#pragma unroll
    for (int oo = 0; oo < 4; oo++) {
        float bv = bias[((o0 + oo) * OH_ + h) * OW_ + w];
#pragma unroll
        for (int bb = 0; bb < 4; bb++) {
            out[(((size_t)(b0 + bb) * COUT_ + (o0 + oo)) * OH_ + h) * OW_ + w]
                = acc[bb][oo] + bv;
        }
    }
}

extern "C" void kernel_launch(void* const* d_in, const int* in_sizes, int n_in,
                              void* d_out, int out_size)
{
    const float* x    = (const float*)d_in[0];   // [32,32,64,64]
    const float* wgt  = (const float*)d_in[1];   // [64,64,64,32,3,3]
    const float* bias = (const float*)d_in[2];   // [64,64,64]
    float* out = (float*)d_out;                  // [32,64,64,64]

    dim3 grid(OW_, OH_);
    lc_conv_kernel<<<grid, 128>>>(x, wgt, bias, out);
}

// round 3
// speedup vs baseline: 1.2649x; 1.2649x over previous
#include <cuda_runtime.h>

// Locally-connected conv, per-(h,w) GEMM: M=B=32, N=COUT=64, K=288.
// CTA = 128 threads = 2 adjacent positions (w, w+1), sharing a 4-column patch stage.
// Per thread: 4b x 8o tile, accumulated as f32x2 pairs (fma.rn.f32x2).

#define B_    32
#define CIN_  32
#define IH_   64
#define IW_   64
#define COUT_ 64
#define OH_   64
#define OW_   64
#define KTOT  288
#define NCI   96      // CIN_*3  (c,i) pairs
#define CIPC  8       // ci per chunk
#define KCH   24      // k per chunk = CIPC*3
#define NCHK  12      // NCI/CIPC

#define PS_FLOATS (NCI * 4 * 32)    // 12288 floats = 48 KB  (ci, 4 cols, 32 b)
#define WS_HALF   (KCH * COUT_)     // 1536 floats per position chunk
#define WS_FLOATS (2 * WS_HALF)     // 3072 floats = 12 KB
#define SMEM_BYTES ((PS_FLOATS + WS_FLOATS) * 4)   // 61440 B

typedef unsigned long long u64;

__device__ __forceinline__ u64 pk2(float v) {
    u64 r; asm("mov.b64 %0, {%1,%2};" : "=l"(r) : "f"(v), "f"(v)); return r;
}
__device__ __forceinline__ void fma2(u64& d, u64 a, u64 b) {
    asm("fma.rn.f32x2 %0, %1, %2, %0;" : "+l"(d) : "l"(a), "l"(b));
}
__device__ __forceinline__ void upk2(u64 v, float& lo, float& hi) {
    asm("mov.b64 {%0,%1}, %2;" : "=f"(lo), "=f"(hi) : "l"(v));
}
// LDS.128 returning two packed f32x2 (w[o],w[o+1]),(w[o+2],w[o+3])
__device__ __forceinline__ void lds_w2(u64& a, u64& b, const float* p) {
    unsigned addr = (unsigned)__cvta_generic_to_shared(p);
    asm volatile("ld.shared.v2.b64 {%0,%1}, [%2];" : "=l"(a), "=l"(b) : "r"(addr));
}

__global__ __launch_bounds__(128)
void lc_conv2(const float* __restrict__ x,
              const float* __restrict__ wgt,
              const float* __restrict__ bias,
              float* __restrict__ out)
{
    extern __shared__ float smem[];
    float* ps = smem;                 // [ci][jj 0..3][b]
    float* ws = smem + PS_FLOATS;     // [half][kk][o]

    const int bx   = blockIdx.x;      // w-pair index
    const int h    = blockIdx.y;
    const int t    = threadIdx.x;
    const int half = t >> 6;          // position within pair
    const int t6   = t & 63;
    const int w    = bx * 2 + half;
    const int b0   = (t6 & 7) * 4;
    const int o0   = (t6 >> 3) * 8;

    // ---- weight prefetch: thread t6 owns output row o = t6 of its position ----
    const float4* wrow = (const float4*)(wgt + ((size_t)(h * OW_ + w) * COUT_ + t6) * KTOT);
    float4 r[6];
#pragma unroll
    for (int i = 0; i < 6; i++) r[i] = wrow[i];   // chunk 0 (overlaps patch staging)

    // ---- stage patches: columns (2bx-1 .. 2bx+2), transposed [k-ish][b] ----
    const int wc0 = bx * 2 - 1;
    for (int u = t; u < NCI * 32; u += 128) {
        int b  = u & 31;
        int ci = u >> 5;
        int c  = ci / 3, i = ci - c * 3;
        int row = h + i - 1;
        float v0 = 0.f, v1 = 0.f, v2 = 0.f, v3 = 0.f;
        if ((unsigned)row < IH_) {
            const float* xp = x + ((b * CIN_ + c) * IH_ + row) * IW_;
            int c0 = wc0;
            if ((unsigned)(c0 + 0) < IW_) v0 = xp[c0 + 0];
            if ((unsigned)(c0 + 1) < IW_) v1 = xp[c0 + 1];
            if ((unsigned)(c0 + 2) < IW_) v2 = xp[c0 + 2];
            if ((unsigned)(c0 + 3) < IW_) v3 = xp[c0 + 3];
        }
        float* pp = ps + ci * 4 * 32 + b;
        pp[0]  = v0; pp[32] = v1; pp[64] = v2; pp[96] = v3;
    }

    u64 acc[4][4];
#pragma unroll
    for (int bb = 0; bb < 4; bb++)
#pragma unroll
        for (int op = 0; op < 4; op++) acc[bb][op] = 0ull;

    float* wsh = ws + half * WS_HALF;

    // ---- main loop over K chunks ----
    for (int ck = 0; ck < NCHK; ck++) {
        __syncthreads();                       // prior compute done; ws reusable
        // store prefetched chunk transposed to [kk][o]
#pragma unroll
        for (int q = 0; q < 6; q++) {
            float* wp = wsh + (q * 4) * COUT_ + t6;
            wp[0 * COUT_] = r[q].x;
            wp[1 * COUT_] = r[q].y;
            wp[2 * COUT_] = r[q].z;
            wp[3 * COUT_] = r[q].w;
        }
        __syncthreads();                       // ws ready

        if (ck + 1 < NCHK) {                   // issue next chunk's LDGs early
#pragma unroll
            for (int i = 0; i < 6; i++) r[i] = wrow[(ck + 1) * 6 + i];
        }

        // compute: 8 ci x 3 j, 16 fma2 each
#pragma unroll
        for (int cil = 0; cil < CIPC; cil++) {
            const float* ab = ps + ((ck * CIPC + cil) * 4 + half) * 32 + b0;
            float4 a0 = *(const float4*)(ab);
            float4 a1 = *(const float4*)(ab + 32);
            float4 a2 = *(const float4*)(ab + 64);
            const float* wb = wsh + (cil * 3) * COUT_ + o0;
#pragma unroll
            for (int j = 0; j < 3; j++) {
                u64 w01, w23, w45, w67;
                lds_w2(w01, w23, wb + j * COUT_);
                lds_w2(w45, w67, wb + j * COUT_ + 4);
                float4 a = (j == 0) ? a0 : ((j == 1) ? a1 : a2);
                u64 p0 = pk2(a.x), p1 = pk2(a.y), p2 = pk2(a.z), p3 = pk2(a.w);
                fma2(acc[0][0], p0, w01); fma2(acc[0][1], p0, w23);
                fma2(acc[0][2], p0, w45); fma2(acc[0][3], p0, w67);
                fma2(acc[1][0], p1, w01); fma2(acc[1][1], p1, w23);
                fma2(acc[1][2], p1, w45); fma2(acc[1][3], p1, w67);
                fma2(acc[2][0], p2, w01); fma2(acc[2][1], p2, w23);
                fma2(acc[2][2], p2, w45); fma2(acc[2][3], p2, w67);
                fma2(acc[3][0], p3, w01); fma2(acc[3][1], p3, w23);
                fma2(acc[3][2], p3, w45); fma2(acc[3][3], p3, w67);
            }
        }
    }

    // ---- epilogue: bias + store ----
#pragma unroll
    for (int op = 0; op < 4; op++) {
        int o = o0 + 2 * op;
        float blo = bias[(o * OH_ + h) * OW_ + w];
        float bhi = bias[((o + 1) * OH_ + h) * OW_ + w];
#pragma unroll
        for (int bb = 0; bb < 4; bb++) {
            float lo, hi; upk2(acc[bb][op], lo, hi);
            size_t base = (((size_t)(b0 + bb) * COUT_ + o) * OH_ + h) * OW_ + w;
            out[base]                        = lo + blo;
            out[base + (size_t)OH_ * OW_]    = hi + bhi;
        }
    }
}

extern "C" void kernel_launch(void* const* d_in, const int* in_sizes, int n_in,
                              void* d_out, int out_size)
{
    const float* x    = (const float*)d_in[0];   // [32,32,64,64]
    const float* wgt  = (const float*)d_in[1];   // [64,64,64,32,3,3]
    const float* bias = (const float*)d_in[2];   // [64,64,64]
    float* out = (float*)d_out;                  // [32,64,64,64]

    cudaFuncSetAttribute(lc_conv2, cudaFuncAttributeMaxDynamicSharedMemorySize, SMEM_BYTES);
    dim3 grid(OW_ / 2, OH_);
    lc_conv2<<<grid, 128, SMEM_BYTES>>>(x, wgt, bias, out);
}

// round 4
// speedup vs baseline: 1.2771x; 1.0097x over previous
#include <cuda_runtime.h>

// Locally-connected conv, per-(h,w) GEMM: M=B=32, N=COUT=64, K=288.
// CTA = 128 threads = 2 adjacent positions (w, w+1).
// BOTH operands streamed through double-buffered smem chunks; one sync/chunk.
// Per thread: 4b x 8o tile accumulated as f32x2 pairs (fma.rn.f32x2).

#define B_    32
#define CIN_  32
#define IH_   64
#define IW_   64
#define COUT_ 64
#define OH_   64
#define OW_   64
#define KTOT  288
#define CIPC  8                   // ci per chunk
#define NCHK  12                  // 96 / CIPC
#define PS_CH (CIPC * 4 * 32)     // 1024 floats / buffer
#define WS_CH (2 * CIPC * 3 * COUT_) // 3072 floats / buffer (2 positions)

typedef unsigned long long u64;

__device__ __forceinline__ u64 pk2(float v) {
    u64 r; asm("mov.b64 %0, {%1,%2};" : "=l"(r) : "f"(v), "f"(v)); return r;
}
__device__ __forceinline__ void fma2(u64& d, u64 a, u64 b) {
    asm("fma.rn.f32x2 %0, %1, %2, %0;" : "+l"(d) : "l"(a), "l"(b));
}
__device__ __forceinline__ void upk2(u64 v, float& lo, float& hi) {
    asm("mov.b64 {%0,%1}, %2;" : "=f"(lo), "=f"(hi) : "l"(v));
}

__global__ __launch_bounds__(128)
void lc_conv3(const float* __restrict__ x,
              const float* __restrict__ wgt,
              const float* __restrict__ bias,
              float* __restrict__ out)
{
    __shared__ float ps[2][PS_CH];   // [buf][cil][col 0..3][b]
    __shared__ float ws[2][WS_CH];   // [buf][half][kk][o]

    const int bx   = blockIdx.x;
    const int h    = blockIdx.y;
    const int t    = threadIdx.x;
    const int half = t >> 6;
    const int t6   = t & 63;
    const int w    = bx * 2 + half;
    const int b0   = (t6 & 7) * 4;
    const int o0   = (t6 >> 3) * 8;
    const int wc0  = bx * 2 - 1;

    // column validity (constant over chunks)
    bool colok[4];
#pragma unroll
    for (int cc = 0; cc < 4; cc++) colok[cc] = (unsigned)(wc0 + cc) < IW_;

    // patch staging assignment: units u = t and t+128
    const int pb0  = t & 31;          // b
    const int cilA = t >> 5;          // cil 0..3
    const int cilB = cilA + 4;        // cil 4..7

    // weight row for this thread's position
    const float4* wrow = (const float4*)(wgt + ((size_t)(h * OW_ + w) * COUT_ + t6) * KTOT);

    // ---------------- prefetch chunk 0 ----------------
    float4 r[6];
#pragma unroll
    for (int i = 0; i < 6; i++) r[i] = wrow[i];

    float pv[2][4];
#pragma unroll
    for (int uu = 0; uu < 2; uu++) {
        int ci = (uu == 0) ? cilA : cilB;            // chunk 0: ci = cil
        int c = ci / 3, ii = ci - c * 3;
        int row = h + ii - 1;
#pragma unroll
        for (int cc = 0; cc < 4; cc++) pv[uu][cc] = 0.0f;
        if ((unsigned)row < IH_) {
            const float* xp = x + ((pb0 * CIN_ + c) * IH_ + row) * IW_ + wc0;
#pragma unroll
            for (int cc = 0; cc < 4; cc++) if (colok[cc]) pv[uu][cc] = xp[cc];
        }
    }

    u64 acc[4][4];
#pragma unroll
    for (int bb = 0; bb < 4; bb++)
#pragma unroll
        for (int op = 0; op < 4; op++) acc[bb][op] = 0ull;

    // ---------------- main loop ----------------
    for (int ck = 0; ck < NCHK; ck++) {
        const int sel = ck & 1;
        float* psb = ps[sel];
        float* wsb = ws[sel] + half * (CIPC * 3 * COUT_);

        // store prefetched patch chunk
#pragma unroll
        for (int uu = 0; uu < 2; uu++) {
            int cil = (uu == 0) ? cilA : cilB;
            float* pp = psb + cil * (4 * 32) + pb0;
            pp[0] = pv[uu][0]; pp[32] = pv[uu][1]; pp[64] = pv[uu][2]; pp[96] = pv[uu][3];
        }
        // store prefetched weight chunk, transposed to [kk][o]
#pragma unroll
        for (int q = 0; q < 6; q++) {
            float* wp = wsb + (q * 4) * COUT_ + t6;
            wp[0 * COUT_] = r[q].x;
            wp[1 * COUT_] = r[q].y;
            wp[2 * COUT_] = r[q].z;
            wp[3 * COUT_] = r[q].w;
        }
        __syncthreads();

        // issue next chunk's global loads (latency hidden under compute)
        if (ck + 1 < NCHK) {
#pragma unroll
            for (int i = 0; i < 6; i++) r[i] = wrow[(ck + 1) * 6 + i];
#pragma unroll
            for (int uu = 0; uu < 2; uu++) {
                int ci = (ck + 1) * CIPC + ((uu == 0) ? cilA : cilB);
                int c = ci / 3, ii = ci - c * 3;
                int row = h + ii - 1;
#pragma unroll
                for (int cc = 0; cc < 4; cc++) pv[uu][cc] = 0.0f;
                if ((unsigned)row < IH_) {
                    const float* xp = x + ((pb0 * CIN_ + c) * IH_ + row) * IW_ + wc0;
#pragma unroll
                    for (int cc = 0; cc < 4; cc++) if (colok[cc]) pv[uu][cc] = xp[cc];
                }
            }
        }

        // compute: 8 ci x 3 j, 16 fma2 each (compiler-schedulable smem loads)
#pragma unroll
        for (int cil = 0; cil < CIPC; cil++) {
            const float* ab = psb + cil * (4 * 32) + half * 32 + b0;
            float4 a0 = *(const float4*)(ab);
            float4 a1 = *(const float4*)(ab + 32);
            float4 a2 = *(const float4*)(ab + 64);
            const float* wb = wsb + (cil * 3) * COUT_ + o0;
#pragma unroll
            for (int j = 0; j < 3; j++) {
                ulonglong2 wlo = *(const ulonglong2*)(wb + j * COUT_);
                ulonglong2 whi = *(const ulonglong2*)(wb + j * COUT_ + 4);
                u64 w01 = wlo.x, w23 = wlo.y, w45 = whi.x, w67 = whi.y;
                float4 a = (j == 0) ? a0 : ((j == 1) ? a1 : a2);
                u64 p0 = pk2(a.x), p1 = pk2(a.y), p2 = pk2(a.z), p3 = pk2(a.w);
                fma2(acc[0][0], p0, w01); fma2(acc[0][1], p0, w23);
                fma2(acc[0][2], p0, w45); fma2(acc[0][3], p0, w67);
                fma2(acc[1][0], p1, w01); fma2(acc[1][1], p1, w23);
                fma2(acc[1][2], p1, w45); fma2(acc[1][3], p1, w67);
                fma2(acc[2][0], p2, w01); fma2(acc[2][1], p2, w23);
                fma2(acc[2][2], p2, w45); fma2(acc[2][3], p2, w67);
                fma2(acc[3][0], p3, w01); fma2(acc[3][1], p3, w23);
                fma2(acc[3][2], p3, w45); fma2(acc[3][3], p3, w67);
            }
        }
    }

    // ---------------- epilogue: bias + store ----------------
#pragma unroll
    for (int op = 0; op < 4; op++) {
        int o = o0 + 2 * op;
        float blo = bias[(o * OH_ + h) * OW_ + w];
        float bhi = bias[((o + 1) * OH_ + h) * OW_ + w];
#pragma unroll
        for (int bb = 0; bb < 4; bb++) {
            float lo, hi; upk2(acc[bb][op], lo, hi);
            size_t base = (((size_t)(b0 + bb) * COUT_ + o) * OH_ + h) * OW_ + w;
            out[base]                     = lo + blo;
            out[base + (size_t)OH_ * OW_] = hi + bhi;
        }
    }
}

extern "C" void kernel_launch(void* const* d_in, const int* in_sizes, int n_in,
                              void* d_out, int out_size)
{
    const float* x    = (const float*)d_in[0];   // [32,32,64,64]
    const float* wgt  = (const float*)d_in[1];   // [64,64,64,32,3,3]
    const float* bias = (const float*)d_in[2];   // [64,64,64]
    float* out = (float*)d_out;                  // [32,64,64,64]

    dim3 grid(OW_ / 2, OH_);
    lc_conv3<<<grid, 128>>>(x, wgt, bias, out);
}

// round 6
// speedup vs baseline: 1.2776x; 1.0003x over previous
#include <cuda_runtime.h>

// Locally-connected conv, per-(h,w) GEMM: M=B=32, N=COUT=64, K=288.
// CTA = 128 threads = 2 adjacent positions (w, w+1).
// BOTH operands streamed through double-buffered smem chunks; one sync/chunk.
// Per thread: 4b x 8o tile accumulated as f32x2 pairs (fma.rn.f32x2).

#define B_    32
#define CIN_  32
#define IH_   64
#define IW_   64
#define COUT_ 64
#define OH_   64
#define OW_   64
#define KTOT  288
#define CIPC  8                   // ci per chunk
#define NCHK  12                  // 96 / CIPC
#define PS_CH (CIPC * 4 * 32)     // 1024 floats / buffer
#define WS_CH (2 * CIPC * 3 * COUT_) // 3072 floats / buffer (2 positions)

typedef unsigned long long u64;

__device__ __forceinline__ u64 pk2(float v) {
    u64 r; asm("mov.b64 %0, {%1,%2};" : "=l"(r) : "f"(v), "f"(v)); return r;
}
__device__ __forceinline__ void fma2(u64& d, u64 a, u64 b) {
    asm("fma.rn.f32x2 %0, %1, %2, %0;" : "+l"(d) : "l"(a), "l"(b));
}
__device__ __forceinline__ void upk2(u64 v, float& lo, float& hi) {
    asm("mov.b64 {%0,%1}, %2;" : "=f"(lo), "=f"(hi) : "l"(v));
}

__global__ __launch_bounds__(128)
void lc_conv3(const float* __restrict__ x,
              const float* __restrict__ wgt,
              const float* __restrict__ bias,
              float* __restrict__ out)
{
    __shared__ float ps[2][PS_CH];   // [buf][cil][col 0..3][b]
    __shared__ float ws[2][WS_CH];   // [buf][half][kk][o]

    const int bx   = blockIdx.x;
    const int h    = blockIdx.y;
    const int t    = threadIdx.x;
    const int half = t >> 6;
    const int t6   = t & 63;
    const int w    = bx * 2 + half;
    const int b0   = (t6 & 7) * 4;
    const int o0   = (t6 >> 3) * 8;
    const int wc0  = bx * 2 - 1;

    // column validity (constant over chunks)
    bool colok[4];
#pragma unroll
    for (int cc = 0; cc < 4; cc++) colok[cc] = (unsigned)(wc0 + cc) < IW_;

    // patch staging assignment: units u = t and t+128
    const int pb0  = t & 31;          // b
    const int cilA = t >> 5;          // cil 0..3
    const int cilB = cilA + 4;        // cil 4..7

    // weight row for this thread's position
    const float4* wrow = (const float4*)(wgt + ((size_t)(h * OW_ + w) * COUT_ + t6) * KTOT);

    // ---------------- prefetch chunk 0 ----------------
    float4 r[6];
#pragma unroll
    for (int i = 0; i < 6; i++) r[i] = wrow[i];

    float pv[2][4];
#pragma unroll
    for (int uu = 0; uu < 2; uu++) {
        int ci = (uu == 0) ? cilA : cilB;            // chunk 0: ci = cil
        int c = ci / 3, ii = ci - c * 3;
        int row = h + ii - 1;
#pragma unroll
        for (int cc = 0; cc < 4; cc++) pv[uu][cc] = 0.0f;
        if ((unsigned)row < IH_) {
            const float* xp = x + ((pb0 * CIN_ + c) * IH_ + row) * IW_ + wc0;
#pragma unroll
            for (int cc = 0; cc < 4; cc++) if (colok[cc]) pv[uu][cc] = xp[cc];
        }
    }

    u64 acc[4][4];
#pragma unroll
    for (int bb = 0; bb < 4; bb++)
#pragma unroll
        for (int op = 0; op < 4; op++) acc[bb][op] = 0ull;

    // ---------------- main loop ----------------
    for (int ck = 0; ck < NCHK; ck++) {
        const int sel = ck & 1;
        float* psb = ps[sel];
        float* wsb = ws[sel] + half * (CIPC * 3 * COUT_);

        // store prefetched patch chunk
#pragma unroll
        for (int uu = 0; uu < 2; uu++) {
            int cil = (uu == 0) ? cilA : cilB;
            float* pp = psb + cil * (4 * 32) + pb0;
            pp[0] = pv[uu][0]; pp[32] = pv[uu][1]; pp[64] = pv[uu][2]; pp[96] = pv[uu][3];
        }
        // store prefetched weight chunk, transposed to [kk][o]
#pragma unroll
        for (int q = 0; q < 6; q++) {
            float* wp = wsb + (q * 4) * COUT_ + t6;
            wp[0 * COUT_] = r[q].x;
            wp[1 * COUT_] = r[q].y;
            wp[2 * COUT_] = r[q].z;
            wp[3 * COUT_] = r[q].w;
        }
        __syncthreads();

        // issue next chunk's global loads (latency hidden under compute)
        if (ck + 1 < NCHK) {
#pragma unroll
            for (int i = 0; i < 6; i++) r[i] = wrow[(ck + 1) * 6 + i];
#pragma unroll
            for (int uu = 0; uu < 2; uu++) {
                int ci = (ck + 1) * CIPC + ((uu == 0) ? cilA : cilB);
                int c = ci / 3, ii = ci - c * 3;
                int row = h + ii - 1;
#pragma unroll
                for (int cc = 0; cc < 4; cc++) pv[uu][cc] = 0.0f;
                if ((unsigned)row < IH_) {
                    const float* xp = x + ((pb0 * CIN_ + c) * IH_ + row) * IW_ + wc0;
#pragma unroll
                    for (int cc = 0; cc < 4; cc++) if (colok[cc]) pv[uu][cc] = xp[cc];
                }
            }
        }

        // compute: 8 ci x 3 j, 16 fma2 each (compiler-schedulable smem loads)
#pragma unroll
        for (int cil = 0; cil < CIPC; cil++) {
            const float* ab = psb + cil * (4 * 32) + half * 32 + b0;
            float4 a0 = *(const float4*)(ab);
            float4 a1 = *(const float4*)(ab + 32);
            float4 a2 = *(const float4*)(ab + 64);
            const float* wb = wsb + (cil * 3) * COUT_ + o0;
#pragma unroll
            for (int j = 0; j < 3; j++) {
                ulonglong2 wlo = *(const ulonglong2*)(wb + j * COUT_);
                ulonglong2 whi = *(const ulonglong2*)(wb + j * COUT_ + 4);
                u64 w01 = wlo.x, w23 = wlo.y, w45 = whi.x, w67 = whi.y;
                float4 a = (j == 0) ? a0 : ((j == 1) ? a1 : a2);
                u64 p0 = pk2(a.x), p1 = pk2(a.y), p2 = pk2(a.z), p3 = pk2(a.w);
                fma2(acc[0][0], p0, w01); fma2(acc[0][1], p0, w23);
                fma2(acc[0][2], p0, w45); fma2(acc[0][3], p0, w67);
                fma2(acc[1][0], p1, w01); fma2(acc[1][1], p1, w23);
                fma2(acc[1][2], p1, w45); fma2(acc[1][3], p1, w67);
                fma2(acc[2][0], p2, w01); fma2(acc[2][1], p2, w23);
                fma2(acc[2][2], p2, w45); fma2(acc[2][3], p2, w67);
                fma2(acc[3][0], p3, w01); fma2(acc[3][1], p3, w23);
                fma2(acc[3][2], p3, w45); fma2(acc[3][3], p3, w67);
            }
        }
    }

    // ---------------- epilogue: bias + store ----------------
#pragma unroll
    for (int op = 0; op < 4; op++) {
        int o = o0 + 2 * op;
        float blo = bias[(o * OH_ + h) * OW_ + w];
        float bhi = bias[((o + 1) * OH_ + h) * OW_ + w];
#pragma unroll
        for (int bb = 0; bb < 4; bb++) {
            float lo, hi; upk2(acc[bb][op], lo, hi);
            size_t base = (((size_t)(b0 + bb) * COUT_ + o) * OH_ + h) * OW_ + w;
            out[base]                     = lo + blo;
            out[base + (size_t)OH_ * OW_] = hi + bhi;
        }
    }
}

extern "C" void kernel_launch(void* const* d_in, const int* in_sizes, int n_in,
                              void* d_out, int out_size)
{
    const float* x    = (const float*)d_in[0];   // [32,32,64,64]
    const float* wgt  = (const float*)d_in[1];   // [64,64,64,32,3,3]
    const float* bias = (const float*)d_in[2];   // [64,64,64]
    float* out = (float*)d_out;                  // [32,64,64,64]

    dim3 grid(OW_ / 2, OH_);
    lc_conv3<<<grid, 128>>>(x, wgt, bias, out);
}